// round 4
// baseline (speedup 1.0000x reference)
#include <cuda_runtime.h>
#include <cuda_bf16.h>
#include <cuda_fp16.h>
#include <cstdint>

// ---------------- problem constants ----------------
#define NB 64
#define NS 1024
#define NH 512
#define NM (NB*NS)          // 65536 rows
#define PLANE ((size_t)NM*NH)

// GEMM tiling
#define BM 128
#define BN 256
#define BK 32
#define ROWE 40             // padded row length (elems); 80 bytes
#define ROWB 80
#define A_SLOT (BM*ROWB)    // 10240
#define B_SLOT (BN*ROWB)    // 20480
#define SLOT (A_SLOT+B_SLOT)
#define SMEM_BYTES (4*SLOT) // 122880

// ---------------- device scratch ----------------
__device__ __nv_bfloat16 g_x_hi [PLANE];   // layer input x (split of `input`)
__device__ __nv_bfloat16 g_x_lo [PLANE];
__device__ __nv_bfloat16 g_rh_hi[PLANE];   // r*h
__device__ __nv_bfloat16 g_rh_lo[PLANE];
__device__ __nv_bfloat16 g_h_hi [3*PLANE]; // h outputs per layer
__device__ __nv_bfloat16 g_h_lo [3*PLANE];
__device__ __half        g_zp   [PLANE];   // z gate (fp16)
__device__ __nv_bfloat16 g_wzr_hi[(size_t)3*1024*512]; // [z|r] weights^T per layer
__device__ __nv_bfloat16 g_wzr_lo[(size_t)3*1024*512];
__device__ __nv_bfloat16 g_wg_hi [(size_t)3*512*1024]; // [Wgx;Wgh]^T per layer (row stride 1024)
__device__ __nv_bfloat16 g_wg_lo [(size_t)3*512*1024];
__device__ __nv_bfloat16 g_wo_hi [(size_t)512*512];
__device__ __nv_bfloat16 g_wo_lo [(size_t)512*512];
__device__ float g_hz [NB*NH];
__device__ float g_hr [NB*NH];
__device__ float g_h0c[NB*NH];

// ---------------- helpers ----------------
__device__ __forceinline__ uint32_t smem_u32(const void* p) {
    uint32_t a;
    asm("{ .reg .u64 t; cvta.to.shared.u64 t, %1; cvt.u32.u64 %0, t; }" : "=r"(a) : "l"(p));
    return a;
}
__device__ __forceinline__ void cp_async16(uint32_t dst, const void* src) {
    asm volatile("cp.async.cg.shared.global [%0], [%1], 16;" :: "r"(dst), "l"(src) : "memory");
}
__device__ __forceinline__ void cp_commit() { asm volatile("cp.async.commit_group;" ::: "memory"); }
__device__ __forceinline__ void cp_wait2()  { asm volatile("cp.async.wait_group 2;" ::: "memory"); }
__device__ __forceinline__ void ldmatrix4(uint32_t& r0, uint32_t& r1, uint32_t& r2, uint32_t& r3, uint32_t addr) {
    asm volatile("ldmatrix.sync.aligned.m8n8.x4.shared.b16 {%0,%1,%2,%3}, [%4];"
                 : "=r"(r0), "=r"(r1), "=r"(r2), "=r"(r3) : "r"(addr));
}
__device__ __forceinline__ void mma_bf16(float* d, const uint32_t* a, const uint32_t* b) {
    asm volatile("mma.sync.aligned.m16n8k16.row.col.f32.bf16.bf16.f32 "
        "{%0,%1,%2,%3}, {%4,%5,%6,%7}, {%8,%9}, {%0,%1,%2,%3};"
        : "+f"(d[0]), "+f"(d[1]), "+f"(d[2]), "+f"(d[3])
        : "r"(a[0]), "r"(a[1]), "r"(a[2]), "r"(a[3]), "r"(b[0]), "r"(b[1]));
}
__device__ __forceinline__ void split2(float v, __nv_bfloat16& hi, __nv_bfloat16& lo) {
    hi = __float2bfloat16(v);
    lo = __float2bfloat16(v - __bfloat162float(hi));
}

// ---------------- prep kernels ----------------
__global__ void k_split(const float4* __restrict__ x,
                        __nv_bfloat16* __restrict__ hi, __nv_bfloat16* __restrict__ lo) {
    size_t i = (size_t)blockIdx.x * blockDim.x + threadIdx.x;
    float4 v = x[i];
    float a[4] = {v.x, v.y, v.z, v.w};
    #pragma unroll
    for (int j = 0; j < 4; j++) {
        __nv_bfloat16 h, l; split2(a[j], h, l);
        hi[4*i + j] = h; lo[4*i + j] = l;
    }
}

// Transpose + (optional add) + split: dst[(n)*dstride + k] = W[k][n] (+ W2[k][n])
__global__ void k_wprep(const float* __restrict__ W, const float* __restrict__ W2,
                        __nv_bfloat16* __restrict__ hi, __nv_bfloat16* __restrict__ lo,
                        int dstride) {
    __shared__ float t[32][33];
    int k0 = blockIdx.y * 32, n0 = blockIdx.x * 32;
    for (int r = threadIdx.y; r < 32; r += 8) {
        float v = W[(size_t)(k0 + r) * 512 + n0 + threadIdx.x];
        if (W2) v += W2[(size_t)(k0 + r) * 512 + n0 + threadIdx.x];
        t[r][threadIdx.x] = v;
    }
    __syncthreads();
    for (int r = threadIdx.y; r < 32; r += 8) {
        float v = t[threadIdx.x][r];
        __nv_bfloat16 h, l; split2(v, h, l);
        hi[(size_t)(n0 + r) * dstride + k0 + threadIdx.x] = h;
        lo[(size_t)(n0 + r) * dstride + k0 + threadIdx.x] = l;
    }
}

__global__ void k_pre(const float* __restrict__ hs,
                      const float* __restrict__ Wzh0, const float* __restrict__ Wrh0,
                      float* __restrict__ hz, float* __restrict__ hr, float* __restrict__ h0c) {
    __shared__ float h0s[512];
    int b = blockIdx.x, n = threadIdx.x;
    float h0v = hs[b*3*NH + n];
    h0s[n] = h0v;
    if (blockIdx.y == 0) h0c[b*NH + n] = h0v;
    __syncthreads();
    const float* W = blockIdx.y ? Wrh0 : Wzh0;
    float acc = 0.f;
    #pragma unroll 8
    for (int k = 0; k < 512; k++) acc = fmaf(h0s[k], W[k*512 + n], acc);
    (blockIdx.y ? hr : hz)[b*NH + n] = acc;
}

__global__ void k_tail(const float* __restrict__ hs,
                       const __nv_bfloat16* __restrict__ h0hi, const __nv_bfloat16* __restrict__ h0lo,
                       const __nv_bfloat16* __restrict__ h1hi, const __nv_bfloat16* __restrict__ h1lo,
                       float* __restrict__ out_h) {
    int b = blockIdx.x, n = threadIdx.x;
    size_t last = ((size_t)b*NS + (NS-1)) * (size_t)NH + n;
    out_h[b*3*NH + n]        = hs[b*3*NH + n];
    out_h[b*3*NH + 512 + n]  = __bfloat162float(h0hi[last]) + __bfloat162float(h0lo[last]);
    out_h[b*3*NH + 1024 + n] = __bfloat162float(h1hi[last]) + __bfloat162float(h1lo[last]);
}

// ---------------- fused bf16x3 HMMA GEMM ----------------
// MODE 0 (G1): N=1024 ([z|r] gates), K'=1536. gate0: z=sigmoid(acc+bz+hz) -> fp16 plane
//              gate1: r=sigmoid(acc+br+hr); rh = r*hv -> bf16 hi/lo planes
// MODE 1 (G2): N=512, K'=3072 over [x|rh]@[Wgx;Wgh]. g=tanh(acc+bg);
//              h' = z*hv + (1-z)*g -> bf16 hi/lo planes
// MODE 2 (OUT): N=512, K'=1536, Cf = acc + bo
struct GP {
    const __nv_bfloat16 *Ahi, *Alo;      // x planes
    const __nv_bfloat16 *A2hi, *A2lo;    // rh planes (MODE 1)
    const __nv_bfloat16 *Bhi, *Blo;      // weight slab
    __half* zout;                        // MODE 0
    __nv_bfloat16 *rhhi, *rhlo;          // MODE 0
    const float *bz, *br;                // MODE 0 biases
    const float *hz, *hr;                // layer0 gate h-terms (or null)
    const float* h0c;                    // layer0 hv (or null)
    const __nv_bfloat16 *hvhi, *hvlo;    // layers 1,2 hv planes
    const __half* zin;                   // MODE 1
    const float* bg;                     // MODE 1 bias
    __nv_bfloat16 *Chi, *Clo;            // MODE 1 out
    float* Cf; const float* bo;          // MODE 2
};

template<int MODE>
__global__ void __launch_bounds__(256) gemm_f(const GP p) {
    constexpr int ITERS = (MODE == 1) ? 96 : 48;
    constexpr int BSTR  = (MODE == 1) ? 1024 : 512;
    extern __shared__ char smem_raw[];
    const uint32_t base = smem_u32(smem_raw);
    const int tid = threadIdx.x;
    const int lane = tid & 31;
    const int w = tid >> 5;
    const int wr = w >> 2;          // 0..1 (64 rows)
    const int wc = w & 3;           // 0..3 (64 cols)
    const int bm = blockIdx.y * BM;
    const int bn = blockIdx.x * BN;

    float c[4][8][4];
    #pragma unroll
    for (int i = 0; i < 4; i++)
        #pragma unroll
        for (int j = 0; j < 8; j++)
            #pragma unroll
            for (int e = 0; e < 4; e++) c[i][j][e] = 0.f;

    const uint32_t a_lm = ((wr*64 + ((lane>>3)&1)*8 + (lane&7)) * ROWE + (lane>>4)*8) * 2;
    const uint32_t b_lm = ((wc*64 + (lane>>4)*8 + (lane&7)) * ROWE + ((lane>>3)&1)*8) * 2;

    auto issue = [&](int cidx) {
        const __nv_bfloat16 *ap, *bp;
        int acol, bcol;
        if (MODE == 1) {
            int seg = cidx >> 5, kk = (cidx & 31) << 5;
            bool sec = kk >= 512;
            const __nv_bfloat16* axh = sec ? p.A2hi : p.Ahi;
            const __nv_bfloat16* axl = sec ? p.A2lo : p.Alo;
            ap = (seg == 2) ? axl : axh;
            bp = (seg == 1) ? p.Blo : p.Bhi;
            acol = kk & 511; bcol = kk;
        } else {
            int seg = cidx >> 4, kk = (cidx & 15) << 5;
            ap = (seg == 2) ? p.Alo : p.Ahi;
            bp = (seg == 1) ? p.Blo : p.Bhi;
            acol = kk; bcol = kk;
        }
        const int slot = cidx & 3;
        const uint32_t sA = base + slot * SLOT;
        const uint32_t sB = sA + A_SLOT;
        #pragma unroll
        for (int i = 0; i < 2; i++) {
            int ch = tid + i * 256;
            int row = ch >> 2, cs = ch & 3;
            cp_async16(sA + row * ROWB + cs * 16,
                       ap + (size_t)(bm + row) * 512 + acol + cs * 8);
        }
        #pragma unroll
        for (int i = 0; i < 4; i++) {
            int ch = tid + i * 256;
            int row = ch >> 2, cs = ch & 3;
            cp_async16(sB + row * ROWB + cs * 16,
                       bp + (size_t)(bn + row) * BSTR + bcol + cs * 8);
        }
    };

    issue(0); cp_commit();
    issue(1); cp_commit();
    issue(2); cp_commit();

    for (int it = 0; it < ITERS; it++) {
        cp_wait2();
        __syncthreads();
        if (it + 3 < ITERS) issue(it + 3);
        cp_commit();

        const int slot = it & 3;
        const uint32_t sA = base + slot * SLOT;
        const uint32_t sB = sA + A_SLOT;
        #pragma unroll
        for (int kh = 0; kh < 2; kh++) {
            const uint32_t koffB = kh * 32;
            uint32_t a[4][4], b[8][2];
            #pragma unroll
            for (int mt = 0; mt < 4; mt++)
                ldmatrix4(a[mt][0], a[mt][1], a[mt][2], a[mt][3],
                          sA + a_lm + mt * (16*ROWB) + koffB);
            #pragma unroll
            for (int np = 0; np < 4; np++) {
                uint32_t r0, r1, r2, r3;
                ldmatrix4(r0, r1, r2, r3, sB + b_lm + np * (16*ROWB) + koffB);
                b[np*2][0] = r0;   b[np*2][1] = r1;
                b[np*2+1][0] = r2; b[np*2+1][1] = r3;
            }
            #pragma unroll
            for (int mt = 0; mt < 4; mt++)
                #pragma unroll
                for (int nt = 0; nt < 8; nt++)
                    mma_bf16(c[mt][nt], a[mt], b[nt]);
        }
    }

    // ---- fused epilogue ----
    const int rbase = bm + wr * 64;
    const int cbase = bn + wc * 64;
    const int gate = (MODE == 0) ? (bn >> 9) : 0;   // uniform per CTA
    #pragma unroll
    for (int mt = 0; mt < 4; mt++) {
        #pragma unroll
        for (int er = 0; er < 2; er++) {
            const int gm = rbase + mt*16 + (lane >> 2) + er*8;
            const int bb = gm >> 10;
            #pragma unroll
            for (int nt = 0; nt < 8; nt++) {
                #pragma unroll
                for (int ec = 0; ec < 2; ec++) {
                    const int gn = cbase + nt*8 + (lane & 3)*2 + ec;
                    float v = c[mt][nt][er*2 + ec];
                    if (MODE == 0) {
                        const int gnn = gn & 511;
                        const size_t idx = (size_t)gm * NH + gnn;
                        v += (gate ? p.br : p.bz)[gnn];
                        if (p.hz) v += (gate ? p.hr : p.hz)[bb * NH + gnn];
                        float s = 1.f / (1.f + __expf(-v));
                        if (!gate) {
                            p.zout[idx] = __float2half(s);
                        } else {
                            float hv = p.h0c ? p.h0c[bb * NH + gnn]
                                : __bfloat162float(p.hvhi[idx]) + __bfloat162float(p.hvlo[idx]);
                            float o = s * hv;
                            __nv_bfloat16 h, l; split2(o, h, l);
                            p.rhhi[idx] = h; p.rhlo[idx] = l;
                        }
                    } else if (MODE == 1) {
                        const size_t idx = (size_t)gm * NH + gn;
                        float g = tanhf(v + p.bg[gn]);
                        float z = __half2float(p.zin[idx]);
                        float hv = p.h0c ? p.h0c[bb * NH + gn]
                            : __bfloat162float(p.hvhi[idx]) + __bfloat162float(p.hvlo[idx]);
                        float o = z * hv + (1.f - z) * g;
                        __nv_bfloat16 h, l; split2(o, h, l);
                        p.Chi[idx] = h; p.Clo[idx] = l;
                    } else {
                        p.Cf[(size_t)gm * NH + gn] = v + p.bo[gn];
                    }
                }
            }
        }
    }
}

// ---------------- host ----------------
extern "C" void kernel_launch(void* const* d_in, const int* in_sizes, int n_in,
                              void* d_out, int out_size) {
    const float* input = (const float*)d_in[0];
    const float* hs    = (const float*)d_in[1];
    const float* Wzx   = (const float*)d_in[2];
    const float* bzx   = (const float*)d_in[3];
    const float* Wzh   = (const float*)d_in[4];
    const float* Wrx   = (const float*)d_in[5];
    const float* brx   = (const float*)d_in[6];
    const float* Wrh   = (const float*)d_in[7];
    const float* Wgx   = (const float*)d_in[8];
    const float* bgx   = (const float*)d_in[9];
    const float* Wgh   = (const float*)d_in[10];
    const float* Wout  = (const float*)d_in[11];
    const float* bout  = (const float*)d_in[12];
    float* out = (float*)d_out;

    __nv_bfloat16 *xhi, *xlo, *rhhi, *rhlo, *hhi, *hlo;
    __nv_bfloat16 *wzrH, *wzrL, *wgH, *wgL, *woH, *woL;
    __half* zp;
    float *hz, *hr, *h0c;
    cudaGetSymbolAddress((void**)&xhi,  g_x_hi);
    cudaGetSymbolAddress((void**)&xlo,  g_x_lo);
    cudaGetSymbolAddress((void**)&rhhi, g_rh_hi);
    cudaGetSymbolAddress((void**)&rhlo, g_rh_lo);
    cudaGetSymbolAddress((void**)&hhi,  g_h_hi);
    cudaGetSymbolAddress((void**)&hlo,  g_h_lo);
    cudaGetSymbolAddress((void**)&zp,   g_zp);
    cudaGetSymbolAddress((void**)&wzrH, g_wzr_hi);
    cudaGetSymbolAddress((void**)&wzrL, g_wzr_lo);
    cudaGetSymbolAddress((void**)&wgH,  g_wg_hi);
    cudaGetSymbolAddress((void**)&wgL,  g_wg_lo);
    cudaGetSymbolAddress((void**)&woH,  g_wo_hi);
    cudaGetSymbolAddress((void**)&woL,  g_wo_lo);
    cudaGetSymbolAddress((void**)&hz,   g_hz);
    cudaGetSymbolAddress((void**)&hr,   g_hr);
    cudaGetSymbolAddress((void**)&h0c,  g_h0c);

    cudaFuncSetAttribute(gemm_f<0>, cudaFuncAttributeMaxDynamicSharedMemorySize, SMEM_BYTES);
    cudaFuncSetAttribute(gemm_f<1>, cudaFuncAttributeMaxDynamicSharedMemorySize, SMEM_BYTES);
    cudaFuncSetAttribute(gemm_f<2>, cudaFuncAttributeMaxDynamicSharedMemorySize, SMEM_BYTES);

    // ---- prep ----
    k_split<<<PLANE/4/256, 256>>>((const float4*)input, xhi, xlo);
    k_pre<<<dim3(64,2), 512>>>(hs, Wzh, Wrh, hz, hr, h0c);
    dim3 wg(16,16), wb(32,8);
    const size_t WS = (size_t)512*512;
    for (int l = 0; l < 3; l++) {
        const float* z2 = l ? (Wzh + l*WS) : nullptr;
        const float* r2 = l ? (Wrh + l*WS) : nullptr;
        size_t zroff = (size_t)l*1024*512;
        k_wprep<<<wg,wb>>>(Wzx + l*WS, z2, wzrH + zroff,            wzrL + zroff,            512);
        k_wprep<<<wg,wb>>>(Wrx + l*WS, r2, wzrH + zroff + 512*512,  wzrL + zroff + 512*512,  512);
        size_t goff = (size_t)l*512*1024;
        k_wprep<<<wg,wb>>>(Wgx + l*WS, nullptr, wgH + goff,        wgL + goff,        1024);
        k_wprep<<<wg,wb>>>(Wgh + l*WS, nullptr, wgH + goff + 512,  wgL + goff + 512,  1024);
    }
    k_wprep<<<wg,wb>>>(Wout, nullptr, woH, woL, 512);

    const dim3 g1(4, 512), g2(2, 512), blk(256);

    for (int l = 0; l < 3; l++) {
        const __nv_bfloat16* XH = l ? (hhi + (size_t)(l-1)*PLANE) : xhi;
        const __nv_bfloat16* XL = l ? (hlo + (size_t)(l-1)*PLANE) : xlo;
        GP p{};
        // ---- G1: [z|r] gates ----
        p.Ahi = XH; p.Alo = XL;
        p.Bhi = wzrH + (size_t)l*1024*512; p.Blo = wzrL + (size_t)l*1024*512;
        p.zout = zp; p.rhhi = rhhi; p.rhlo = rhlo;
        p.bz = bzx + l*512; p.br = brx + l*512;
        p.hz = l ? nullptr : hz; p.hr = l ? nullptr : hr;
        p.h0c = l ? nullptr : h0c;
        p.hvhi = XH; p.hvlo = XL;
        gemm_f<0><<<g1, blk, SMEM_BYTES>>>(p);
        // ---- G2: g gate + combine ----
        GP q{};
        q.Ahi = XH; q.Alo = XL; q.A2hi = rhhi; q.A2lo = rhlo;
        q.Bhi = wgH + (size_t)l*512*1024; q.Blo = wgL + (size_t)l*512*1024;
        q.zin = zp; q.bg = bgx + l*512;
        q.h0c = l ? nullptr : h0c;
        q.hvhi = XH; q.hvlo = XL;
        q.Chi = hhi + (size_t)l*PLANE; q.Clo = hlo + (size_t)l*PLANE;
        gemm_f<1><<<g2, blk, SMEM_BYTES>>>(q);
    }
    // ---- output projection ----
    GP o{};
    o.Ahi = hhi + 2*PLANE; o.Alo = hlo + 2*PLANE;
    o.Bhi = woH; o.Blo = woL;
    o.Cf = out; o.bo = bout;
    gemm_f<2><<<g2, blk, SMEM_BYTES>>>(o);

    k_tail<<<64, 512>>>(hs, hhi, hlo, hhi + PLANE, hlo + PLANE, out + PLANE);
}

// round 5
// speedup vs baseline: 1.3483x; 1.3483x over previous
#include <cuda_runtime.h>
#include <cuda_bf16.h>
#include <cstdint>

// ---------------- problem constants ----------------
#define NB 64
#define NS 1024
#define NH 512
#define NM (NB*NS)          // 65536 rows
#define PLANE ((size_t)NM*NH)

// GEMM tiling (R3-proven config)
#define BM 128
#define BN 128
#define BK 32
#define ROWE 40             // padded row length (elems); 80 bytes
#define ROWB 80
#define A_SLOT (BM*ROWB)    // 10240
#define B_SLOT (BN*ROWB)    // 10240
#define SLOT (A_SLOT+B_SLOT)
#define SMEM_BYTES (4*SLOT) // 81920 -> 2 CTAs/SM fit in 228KB

// ---------------- device scratch ----------------
__device__ __nv_bfloat16 g_x_hi [PLANE];   // split of `input`
__device__ __nv_bfloat16 g_x_lo [PLANE];
__device__ __nv_bfloat16 g_rh_hi[PLANE];   // r*h
__device__ __nv_bfloat16 g_rh_lo[PLANE];
__device__ __nv_bfloat16 g_h_hi [3*PLANE]; // h outputs per layer
__device__ __nv_bfloat16 g_h_lo [3*PLANE];
__device__ float         g_zp   [PLANE];   // z gate (fp32)
__device__ __nv_bfloat16 g_wzr_hi[(size_t)3*1024*512]; // [z|r] weights^T per layer
__device__ __nv_bfloat16 g_wzr_lo[(size_t)3*1024*512];
__device__ __nv_bfloat16 g_wg_hi [(size_t)3*512*1024]; // [Wgx;Wgh]^T per layer (row stride 1024)
__device__ __nv_bfloat16 g_wg_lo [(size_t)3*512*1024];
__device__ __nv_bfloat16 g_wo_hi [(size_t)512*512];
__device__ __nv_bfloat16 g_wo_lo [(size_t)512*512];
__device__ float g_hz [NB*NH];
__device__ float g_hr [NB*NH];
__device__ float g_h0c[NB*NH];

// ---------------- helpers ----------------
__device__ __forceinline__ uint32_t smem_u32(const void* p) {
    uint32_t a;
    asm("{ .reg .u64 t; cvta.to.shared.u64 t, %1; cvt.u32.u64 %0, t; }" : "=r"(a) : "l"(p));
    return a;
}
__device__ __forceinline__ void cp_async16(uint32_t dst, const void* src) {
    asm volatile("cp.async.cg.shared.global [%0], [%1], 16;" :: "r"(dst), "l"(src) : "memory");
}
__device__ __forceinline__ void cp_commit() { asm volatile("cp.async.commit_group;" ::: "memory"); }
__device__ __forceinline__ void cp_wait2()  { asm volatile("cp.async.wait_group 2;" ::: "memory"); }
__device__ __forceinline__ void ldmatrix4(uint32_t& r0, uint32_t& r1, uint32_t& r2, uint32_t& r3, uint32_t addr) {
    asm volatile("ldmatrix.sync.aligned.m8n8.x4.shared.b16 {%0,%1,%2,%3}, [%4];"
                 : "=r"(r0), "=r"(r1), "=r"(r2), "=r"(r3) : "r"(addr));
}
__device__ __forceinline__ void mma_bf16(float* d, const uint32_t* a, const uint32_t* b) {
    asm volatile("mma.sync.aligned.m16n8k16.row.col.f32.bf16.bf16.f32 "
        "{%0,%1,%2,%3}, {%4,%5,%6,%7}, {%8,%9}, {%0,%1,%2,%3};"
        : "+f"(d[0]), "+f"(d[1]), "+f"(d[2]), "+f"(d[3])
        : "r"(a[0]), "r"(a[1]), "r"(a[2]), "r"(a[3]), "r"(b[0]), "r"(b[1]));
}
__device__ __forceinline__ void split2(float v, __nv_bfloat16& hi, __nv_bfloat16& lo) {
    hi = __float2bfloat16(v);
    lo = __float2bfloat16(v - __bfloat162float(hi));
}

// ---------------- prep kernels ----------------
__global__ void k_split(const float4* __restrict__ x,
                        __nv_bfloat16* __restrict__ hi, __nv_bfloat16* __restrict__ lo) {
    size_t i = (size_t)blockIdx.x * blockDim.x + threadIdx.x;
    float4 v = x[i];
    float a[4] = {v.x, v.y, v.z, v.w};
    #pragma unroll
    for (int j = 0; j < 4; j++) {
        __nv_bfloat16 h, l; split2(a[j], h, l);
        hi[4*i + j] = h; lo[4*i + j] = l;
    }
}

// Transpose + (optional add) + split: dst[n*dstride + k] = W[k][n] (+ W2[k][n])
__global__ void k_wprep(const float* __restrict__ W, const float* __restrict__ W2,
                        __nv_bfloat16* __restrict__ hi, __nv_bfloat16* __restrict__ lo,
                        int dstride) {
    __shared__ float t[32][33];
    int k0 = blockIdx.y * 32, n0 = blockIdx.x * 32;
    for (int r = threadIdx.y; r < 32; r += 8) {
        float v = W[(size_t)(k0 + r) * 512 + n0 + threadIdx.x];
        if (W2) v += W2[(size_t)(k0 + r) * 512 + n0 + threadIdx.x];
        t[r][threadIdx.x] = v;
    }
    __syncthreads();
    for (int r = threadIdx.y; r < 32; r += 8) {
        float v = t[threadIdx.x][r];
        __nv_bfloat16 h, l; split2(v, h, l);
        hi[(size_t)(n0 + r) * dstride + k0 + threadIdx.x] = h;
        lo[(size_t)(n0 + r) * dstride + k0 + threadIdx.x] = l;
    }
}

__global__ void k_pre(const float* __restrict__ hs,
                      const float* __restrict__ Wzh0, const float* __restrict__ Wrh0,
                      float* __restrict__ hz, float* __restrict__ hr, float* __restrict__ h0c) {
    __shared__ float h0s[512];
    int b = blockIdx.x, n = threadIdx.x;
    float h0v = hs[b*3*NH + n];
    h0s[n] = h0v;
    if (blockIdx.y == 0) h0c[b*NH + n] = h0v;
    __syncthreads();
    const float* W = blockIdx.y ? Wrh0 : Wzh0;
    float acc = 0.f;
    #pragma unroll 8
    for (int k = 0; k < 512; k++) acc = fmaf(h0s[k], W[k*512 + n], acc);
    (blockIdx.y ? hr : hz)[b*NH + n] = acc;
}

__global__ void k_tail(const float* __restrict__ hs,
                       const __nv_bfloat16* __restrict__ h0hi, const __nv_bfloat16* __restrict__ h0lo,
                       const __nv_bfloat16* __restrict__ h1hi, const __nv_bfloat16* __restrict__ h1lo,
                       float* __restrict__ out_h) {
    int b = blockIdx.x, n = threadIdx.x;
    size_t last = ((size_t)b*NS + (NS-1)) * (size_t)NH + n;
    out_h[b*3*NH + n]        = hs[b*3*NH + n];
    out_h[b*3*NH + 512 + n]  = __bfloat162float(h0hi[last]) + __bfloat162float(h0lo[last]);
    out_h[b*3*NH + 1024 + n] = __bfloat162float(h1hi[last]) + __bfloat162float(h1lo[last]);
}

// ---------------- fused bf16x3 HMMA GEMM ----------------
// MODE 0 (G1): N=1024 ([z|r]), K'=1536. cols<512: z=sigmoid(acc+bz+hz) -> fp32 plane
//              cols>=512: r=sigmoid(acc+br+hr); rh = r*hv -> bf16 hi/lo
// MODE 1 (G2): N=512, K'=3072 over [x|rh]@[Wgx;Wgh]. g=tanh(acc+bg);
//              h' = z*hv + (1-z)*g -> bf16 hi/lo
// MODE 2 (OUT): N=512, K'=1536, Cf = acc + bo
struct GP {
    const __nv_bfloat16 *Ahi, *Alo;      // x planes
    const __nv_bfloat16 *A2hi, *A2lo;    // rh planes (MODE 1)
    const __nv_bfloat16 *Bhi, *Blo;      // weight slab
    float* zout;                         // MODE 0
    __nv_bfloat16 *rhhi, *rhlo;          // MODE 0
    const float *bz, *br;                // MODE 0 biases
    const float *hz, *hr;                // layer0 gate h-terms (or null)
    const float* h0c;                    // layer0 hv (or null)
    const __nv_bfloat16 *hvhi, *hvlo;    // layers 1,2 hv planes
    const float* zin;                    // MODE 1
    const float* bg;                     // MODE 1 bias
    __nv_bfloat16 *Chi, *Clo;            // MODE 1 out
    float* Cf; const float* bo;          // MODE 2
};

template<int MODE>
__global__ void __launch_bounds__(256, 2) gemm_f(const GP p) {
    constexpr int ITERS = (MODE == 1) ? 96 : 48;
    constexpr int BSTR  = (MODE == 1) ? 1024 : 512;
    extern __shared__ char smem_raw[];
    const uint32_t base = smem_u32(smem_raw);
    const int tid = threadIdx.x;
    const int lane = tid & 31;
    const int w = tid >> 5;
    const int wr = w >> 2;          // 0..1 (64 rows)
    const int wc = w & 3;           // 0..3 (32 cols)
    const int bm = blockIdx.y * BM;
    const int bn = blockIdx.x * BN;

    float c[4][4][4];
    #pragma unroll
    for (int i = 0; i < 4; i++)
        #pragma unroll
        for (int j = 0; j < 4; j++)
            #pragma unroll
            for (int e = 0; e < 4; e++) c[i][j][e] = 0.f;

    const uint32_t a_lm = ((wr*64 + ((lane>>3)&1)*8 + (lane&7)) * ROWE + (lane>>4)*8) * 2;
    const uint32_t b_lm = ((wc*32 + (lane>>4)*8 + (lane&7)) * ROWE + ((lane>>3)&1)*8) * 2;

    auto issue = [&](int cidx) {
        const __nv_bfloat16 *ap, *bp;
        int acol, bcol;
        if (MODE == 1) {
            int seg = cidx >> 5, kk = (cidx & 31) << 5;
            bool sec = kk >= 512;
            const __nv_bfloat16* axh = sec ? p.A2hi : p.Ahi;
            const __nv_bfloat16* axl = sec ? p.A2lo : p.Alo;
            ap = (seg == 2) ? axl : axh;
            bp = (seg == 1) ? p.Blo : p.Bhi;
            acol = kk & 511; bcol = kk;
        } else {
            int seg = cidx >> 4, kk = (cidx & 15) << 5;
            ap = (seg == 2) ? p.Alo : p.Ahi;
            bp = (seg == 1) ? p.Blo : p.Bhi;
            acol = kk; bcol = kk;
        }
        const int slot = cidx & 3;
        const uint32_t sA = base + slot * SLOT;
        const uint32_t sB = sA + A_SLOT;
        #pragma unroll
        for (int i = 0; i < 2; i++) {
            int ch = tid + i * 256;
            int row = ch >> 2, cs = ch & 3;
            cp_async16(sA + row * ROWB + cs * 16,
                       ap + (size_t)(bm + row) * 512 + acol + cs * 8);
        }
        #pragma unroll
        for (int i = 0; i < 2; i++) {
            int ch = tid + i * 256;
            int row = ch >> 2, cs = ch & 3;
            cp_async16(sB + row * ROWB + cs * 16,
                       bp + (size_t)(bn + row) * BSTR + bcol + cs * 8);
        }
    };

    issue(0); cp_commit();
    issue(1); cp_commit();
    issue(2); cp_commit();

    for (int it = 0; it < ITERS; it++) {
        cp_wait2();
        __syncthreads();
        if (it + 3 < ITERS) issue(it + 3);
        cp_commit();

        const int slot = it & 3;
        const uint32_t sA = base + slot * SLOT;
        const uint32_t sB = sA + A_SLOT;
        #pragma unroll
        for (int kh = 0; kh < 2; kh++) {
            const uint32_t koffB = kh * 32;
            uint32_t a[4][4], b[4][2];
            #pragma unroll
            for (int mt = 0; mt < 4; mt++)
                ldmatrix4(a[mt][0], a[mt][1], a[mt][2], a[mt][3],
                          sA + a_lm + mt * (16*ROWB) + koffB);
            #pragma unroll
            for (int np = 0; np < 2; np++) {
                uint32_t r0, r1, r2, r3;
                ldmatrix4(r0, r1, r2, r3, sB + b_lm + np * (16*ROWB) + koffB);
                b[np*2][0] = r0;   b[np*2][1] = r1;
                b[np*2+1][0] = r2; b[np*2+1][1] = r3;
            }
            #pragma unroll
            for (int mt = 0; mt < 4; mt++)
                #pragma unroll
                for (int nt = 0; nt < 4; nt++)
                    mma_bf16(c[mt][nt], a[mt], b[nt]);
        }
    }

    // ---- fused epilogue ----
    const int rbase = bm + wr * 64;
    const int cbase = bn + wc * 32;
    const int gate = (MODE == 0) ? (bn >> 9) : 0;   // uniform per CTA (BN=128)
    #pragma unroll
    for (int mt = 0; mt < 4; mt++) {
        #pragma unroll
        for (int er = 0; er < 2; er++) {
            const int gm = rbase + mt*16 + (lane >> 2) + er*8;
            const int bb = gm >> 10;
            #pragma unroll
            for (int nt = 0; nt < 4; nt++) {
                #pragma unroll
                for (int ec = 0; ec < 2; ec++) {
                    const int gn = cbase + nt*8 + (lane & 3)*2 + ec;
                    float v = c[mt][nt][er*2 + ec];
                    if (MODE == 0) {
                        const int gnn = gn & 511;
                        const size_t idx = (size_t)gm * NH + gnn;
                        v += (gate ? p.br : p.bz)[gnn];
                        if (p.hz) v += (gate ? p.hr : p.hz)[bb * NH + gnn];
                        float s = 1.f / (1.f + __expf(-v));
                        if (!gate) {
                            p.zout[idx] = s;
                        } else {
                            float hv = p.h0c ? p.h0c[bb * NH + gnn]
                                : __bfloat162float(p.hvhi[idx]) + __bfloat162float(p.hvlo[idx]);
                            float o = s * hv;
                            __nv_bfloat16 h, l; split2(o, h, l);
                            p.rhhi[idx] = h; p.rhlo[idx] = l;
                        }
                    } else if (MODE == 1) {
                        const size_t idx = (size_t)gm * NH + gn;
                        float g = tanhf(v + p.bg[gn]);
                        float z = p.zin[idx];
                        float hv = p.h0c ? p.h0c[bb * NH + gn]
                            : __bfloat162float(p.hvhi[idx]) + __bfloat162float(p.hvlo[idx]);
                        float o = z * hv + (1.f - z) * g;
                        __nv_bfloat16 h, l; split2(o, h, l);
                        p.Chi[idx] = h; p.Clo[idx] = l;
                    } else {
                        p.Cf[(size_t)gm * NH + gn] = v + p.bo[gn];
                    }
                }
            }
        }
    }
}

// ---------------- host ----------------
extern "C" void kernel_launch(void* const* d_in, const int* in_sizes, int n_in,
                              void* d_out, int out_size) {
    const float* input = (const float*)d_in[0];
    const float* hs    = (const float*)d_in[1];
    const float* Wzx   = (const float*)d_in[2];
    const float* bzx   = (const float*)d_in[3];
    const float* Wzh   = (const float*)d_in[4];
    const float* Wrx   = (const float*)d_in[5];
    const float* brx   = (const float*)d_in[6];
    const float* Wrh   = (const float*)d_in[7];
    const float* Wgx   = (const float*)d_in[8];
    const float* bgx   = (const float*)d_in[9];
    const float* Wgh   = (const float*)d_in[10];
    const float* Wout  = (const float*)d_in[11];
    const float* bout  = (const float*)d_in[12];
    float* out = (float*)d_out;

    __nv_bfloat16 *xhi, *xlo, *rhhi, *rhlo, *hhi, *hlo;
    __nv_bfloat16 *wzrH, *wzrL, *wgH, *wgL, *woH, *woL;
    float *zp, *hz, *hr, *h0c;
    cudaGetSymbolAddress((void**)&xhi,  g_x_hi);
    cudaGetSymbolAddress((void**)&xlo,  g_x_lo);
    cudaGetSymbolAddress((void**)&rhhi, g_rh_hi);
    cudaGetSymbolAddress((void**)&rhlo, g_rh_lo);
    cudaGetSymbolAddress((void**)&hhi,  g_h_hi);
    cudaGetSymbolAddress((void**)&hlo,  g_h_lo);
    cudaGetSymbolAddress((void**)&zp,   g_zp);
    cudaGetSymbolAddress((void**)&wzrH, g_wzr_hi);
    cudaGetSymbolAddress((void**)&wzrL, g_wzr_lo);
    cudaGetSymbolAddress((void**)&wgH,  g_wg_hi);
    cudaGetSymbolAddress((void**)&wgL,  g_wg_lo);
    cudaGetSymbolAddress((void**)&woH,  g_wo_hi);
    cudaGetSymbolAddress((void**)&woL,  g_wo_lo);
    cudaGetSymbolAddress((void**)&hz,   g_hz);
    cudaGetSymbolAddress((void**)&hr,   g_hr);
    cudaGetSymbolAddress((void**)&h0c,  g_h0c);

    cudaFuncSetAttribute(gemm_f<0>, cudaFuncAttributeMaxDynamicSharedMemorySize, SMEM_BYTES);
    cudaFuncSetAttribute(gemm_f<1>, cudaFuncAttributeMaxDynamicSharedMemorySize, SMEM_BYTES);
    cudaFuncSetAttribute(gemm_f<2>, cudaFuncAttributeMaxDynamicSharedMemorySize, SMEM_BYTES);

    // ---- prep ----
    k_split<<<PLANE/4/256, 256>>>((const float4*)input, xhi, xlo);
    k_pre<<<dim3(64,2), 512>>>(hs, Wzh, Wrh, hz, hr, h0c);
    dim3 wg(16,16), wb(32,8);
    const size_t WS = (size_t)512*512;
    for (int l = 0; l < 3; l++) {
        const float* z2 = l ? (Wzh + l*WS) : nullptr;
        const float* r2 = l ? (Wrh + l*WS) : nullptr;
        size_t zroff = (size_t)l*1024*512;
        k_wprep<<<wg,wb>>>(Wzx + l*WS, z2, wzrH + zroff,           wzrL + zroff,           512);
        k_wprep<<<wg,wb>>>(Wrx + l*WS, r2, wzrH + zroff + 512*512, wzrL + zroff + 512*512, 512);
        size_t goff = (size_t)l*512*1024;
        k_wprep<<<wg,wb>>>(Wgx + l*WS, nullptr, wgH + goff,       wgL + goff,       1024);
        k_wprep<<<wg,wb>>>(Wgh + l*WS, nullptr, wgH + goff + 512, wgL + goff + 512, 1024);
    }
    k_wprep<<<wg,wb>>>(Wout, nullptr, woH, woL, 512);

    const dim3 g1(8, 512), g2(4, 512), blk(256);

    for (int l = 0; l < 3; l++) {
        const __nv_bfloat16* XH = l ? (hhi + (size_t)(l-1)*PLANE) : xhi;
        const __nv_bfloat16* XL = l ? (hlo + (size_t)(l-1)*PLANE) : xlo;
        GP p{};
        // ---- G1: [z|r] gates ----
        p.Ahi = XH; p.Alo = XL;
        p.Bhi = wzrH + (size_t)l*1024*512; p.Blo = wzrL + (size_t)l*1024*512;
        p.zout = zp; p.rhhi = rhhi; p.rhlo = rhlo;
        p.bz = bzx + l*512; p.br = brx + l*512;
        p.hz = l ? nullptr : hz; p.hr = l ? nullptr : hr;
        p.h0c = l ? nullptr : h0c;
        p.hvhi = XH; p.hvlo = XL;
        gemm_f<0><<<g1, blk, SMEM_BYTES>>>(p);
        // ---- G2: g gate + combine ----
        GP q{};
        q.Ahi = XH; q.Alo = XL; q.A2hi = rhhi; q.A2lo = rhlo;
        q.Bhi = wgH + (size_t)l*512*1024; q.Blo = wgL + (size_t)l*512*1024;
        q.zin = zp; q.bg = bgx + l*512;
        q.h0c = l ? nullptr : h0c;
        q.hvhi = XH; q.hvlo = XL;
        q.Chi = hhi + (size_t)l*PLANE; q.Clo = hlo + (size_t)l*PLANE;
        gemm_f<1><<<g2, blk, SMEM_BYTES>>>(q);
    }
    // ---- output projection ----
    GP o{};
    o.Ahi = hhi + 2*PLANE; o.Alo = hlo + 2*PLANE;
    o.Bhi = woH; o.Blo = woL;
    o.Cf = out; o.bo = bout;
    gemm_f<2><<<g2, blk, SMEM_BYTES>>>(o);

    k_tail<<<64, 512>>>(hs, hhi, hlo, hhi + PLANE, hlo + PLANE, out + PLANE);
}